// round 7
// baseline (speedup 1.0000x reference)
#include <cuda_runtime.h>
#include <math.h>

#define LMAX 20
#define NM   21           // number of m columns (0..20)
#define KVAL 441          // (LMAX+1)^2
#define RANK_ 256
#define BPTS 16           // points per CTA
#define NPV  (BPTS * 2)   // 32 (point,vector) pairs
#define NTHREADS 256
#define PV_STRIDE 65      // padded (coprime with 32 banks)

// --------------------------------------------------------------------------
// Tables: SAME double-precision normd() formulas as the passing round-6
// kernel (product form), just packed as float2 (A,B).
//   Q(m,m)   = g_seed[m] * pmm
//   Q(m+1,m) = g_c1[m] * ct * Q(m,m)
//   Q(l,m)   = A(l,m) * ct * Q(l-1,m) - B(l,m) * Q(l-2,m)
// Plus a precomputed rank permutation (g_pi/g_pj/g_pr) that groups the 256
// rank pairs into 8 warp-groups with near-distinct smem banks for gathers.
// --------------------------------------------------------------------------
__device__ float2 g_AB[NM * NM];
__device__ float  g_seed[NM];
__device__ float  g_c1[NM];
__device__ int    g_pi[RANK_];
__device__ int    g_pj[RANK_];
__device__ int    g_pr[RANK_];

__device__ __forceinline__ double normd(int l, int m) {
    // sqrt( (2l+1)/(4pi) * (l-m)!/(l+m)! ) -- product then one divide
    double p = 1.0;
    for (int k = l - m + 1; k <= l + m; ++k) p *= (double)k;  // (l+m)!/(l-m)!
    return sqrt((2.0 * l + 1.0) / (4.0 * 3.14159265358979323846) / p);
}

__global__ void init_tables_kernel(const int* __restrict__ ri,
                                   const int* __restrict__ rj) {
    int i = threadIdx.x;
    if (i < NM) {
        int m = i;
        double s = normd(m, m);
        if (m > 0) s *= 1.4142135623730951;   // sqrt(2) for m != 0 terms
        g_seed[m] = (float)s;
        g_c1[m] = (m < LMAX)
            ? (float)((2.0 * m + 1.0) * normd(m + 1, m) / normd(m, m))
            : 0.f;
    }
    for (int idx = i; idx < NM * NM; idx += blockDim.x) {
        int l = idx / NM, m = idx % NM;
        float2 ab = make_float2(0.f, 0.f);
        if (l >= m + 2) {
            ab.x = (float)((2.0 * l - 1.0) / (double)(l - m)
                           * normd(l, m) / normd(l - 1, m));
            ab.y = (float)((double)(l + m - 1) / (double)(l - m)
                           * normd(l, m) / normd(l - 2, m));
        }
        g_AB[idx] = ab;
    }
    // Greedy bank-aware grouping of the 256 rank pairs into 8 groups of 32.
    // Correctness holds for ANY permutation; this only shapes conflicts.
    if (i == 0) {
        unsigned cap[8] = {0, 0, 0, 0, 0, 0, 0, 0};
        unsigned mi[8]  = {0, 0, 0, 0, 0, 0, 0, 0};
        unsigned mj[8]  = {0, 0, 0, 0, 0, 0, 0, 0};
        for (int r = 0; r < RANK_; ++r) {
            int ii = ri[r], jj = rj[r];
            unsigned bi = 1u << (ii & 31);
            unsigned bj = 1u << (jj & 31);
            int best = -1;
            for (int g = 0; g < 8 && best < 0; ++g)       // both banks free
                if (cap[g] < 32 && !(mi[g] & bi) && !(mj[g] & bj)) best = g;
            for (int g = 0; g < 8 && best < 0; ++g)       // i-bank free
                if (cap[g] < 32 && !(mi[g] & bi)) best = g;
            for (int g = 0; g < 8 && best < 0; ++g)       // j-bank free
                if (cap[g] < 32 && !(mj[g] & bj)) best = g;
            for (int g = 0; g < 8 && best < 0; ++g)       // any space
                if (cap[g] < 32) best = g;
            int slot = best * 32 + (int)cap[best];
            cap[best]++; mi[best] |= bi; mj[best] |= bj;
            g_pi[slot] = ii; g_pj[slot] = jj; g_pr[slot] = r;
        }
    }
}

// --------------------------------------------------------------------------
// Main kernel: one CTA = BPTS points = 32 (point,vector) pairs.
// Phase 0: warp 0, lane = pv: ct + trig/diagonal chains into s_pv.
// Phase 1: lane = pv; warp w handles m in {w, 15-w, 16+w(w<5)} (balanced).
// Phase 2: thread t owns permuted rank slot t for all points.
// --------------------------------------------------------------------------
__global__ __launch_bounds__(NTHREADS, 1) void sh_kernel(
    const float* __restrict__ coords, float* __restrict__ out, int npts)
{
    extern __shared__ float smem[];
    float*  s_psi  = smem;                               // NPV*KVAL
    float*  s_pv   = s_psi + NPV * KVAL;                 // NPV*PV_STRIDE
    float2* s_AB   = (float2*)(s_pv + NPV * PV_STRIDE);  // 441 float2
    float*  s_seed = (float*)(s_AB + NM * NM);           // 21
    float*  s_c1   = s_seed + NM;                        // 21

    const int t    = threadIdx.x;
    const int warp = t >> 5;
    const int lane = t & 31;
    const int p0   = blockIdx.x * BPTS;

    // Per-thread permuted rank data for phase 2.
    const int pi = g_pi[t];
    const int pj = g_pj[t];
    const int pr = g_pr[t];

    // Stage tables.
    for (int idx = t; idx < NM * NM; idx += NTHREADS) s_AB[idx] = g_AB[idx];
    if (t < NM) { s_seed[t] = g_seed[t]; s_c1[t] = g_c1[t]; }

    // Phase 0: per (point, vector) trig / diagonal chains (32 threads).
    if (t < NPV) {
        int p = t >> 1, v = t & 1;
        float ct = 0.f, st = 0.f, ca = 1.f, sa = 0.f;
        if (p0 + p < npts) {
            const float* cp = coords + (size_t)(p0 + p) * 6 + v * 3;
            float X = cp[0], Yc = cp[1], Z = cp[2];
            float r = sqrtf(X * X + Yc * Yc + Z * Z);
            ct = Z / r;
            ct = fminf(1.f, fmaxf(-1.f, ct));
            st = sqrtf(fmaxf(0.f, 1.f - ct * ct));     // sin(arccos(ct)) >= 0
            float rxy2 = X * X + Yc * Yc;
            if (rxy2 > 0.f) {                          // atan2(0,0)=0
                float irxy = rsqrtf(rxy2);
                ca = X * irxy; sa = Yc * irxy;
            }
        }
        float* pvd = s_pv + t * PV_STRIDE;
        pvd[0] = ct;
        float cm = 1.f, sv = 0.f, pm = 1.f;
        pvd[1] = cm; pvd[22] = sv; pvd[43] = pm;
        #pragma unroll
        for (int m = 1; m <= LMAX; ++m) {
            float cn = cm * ca - sv * sa;              // cos(m*azim)
            sv = cm * sa + sv * ca;                    // sin(m*azim)
            cm = cn;
            pm *= (1.f - 2.f * (float)m) * st;         // Condon-Shortley diag
            pvd[1 + m] = cm; pvd[22 + m] = sv; pvd[43 + m] = pm;
        }
    }
    __syncthreads();

    // Phase 1: lane = pv, warp-uniform balanced m list.
    if (p0 + (lane >> 1) < npts) {
        int mvals[3];
        mvals[0] = warp;                 // rows 21..14
        mvals[1] = 15 - warp;            // rows  6..13
        mvals[2] = 16 + warp;            // rows  5..1 (warps 0..4 only)
        const int nmv = (warp < 5) ? 3 : 2;

        const float* pvd = s_pv + lane * PV_STRIDE;
        const float  ct  = pvd[0];
        float* ps = s_psi + lane * KVAL;

        for (int k = 0; k < nmv; ++k) {
            const int m = mvals[k];
            float cm = pvd[1 + m], sv = pvd[22 + m], pm = pvd[43 + m];
            float q2 = s_seed[m] * pm;                 // l = m
            int base = m * (m + 1);
            if (m) ps[base - m] = q2 * sv;             // warp-uniform branch
            ps[base + m] = q2 * cm;
            if (m < LMAX) {
                float q1 = s_c1[m] * ct * q2;          // l = m+1
                base = (m + 1) * (m + 2);
                if (m) ps[base - m] = q1 * sv;
                ps[base + m] = q1 * cm;
                for (int l = m + 2; l <= LMAX; ++l) {
                    float2 ab = s_AB[l * NM + m];      // one LDS.64 broadcast
                    float qn = ab.x * ct * q1 - ab.y * q2;
                    q2 = q1; q1 = qn;
                    base += 2 * l;                     // = l*(l+1)
                    if (m) ps[base - m] = qn * sv;
                    ps[base + m] = qn * cm;
                }
            }
        }
    }
    __syncthreads();

    // Phase 2: permuted gathered products. Slot t -> rank pr (any perm OK).
    for (int o = t; o < BPTS * RANK_; o += NTHREADS) {
        int p  = o >> 8;                 // o & 255 == t for every iteration
        int gp = p0 + p;
        if (gp < npts) {
            float a = s_psi[(2 * p)     * KVAL + pi];
            float b = s_psi[(2 * p + 1) * KVAL + pj];
            out[(size_t)gp * RANK_ + pr] = a * b;
        }
    }
}

extern "C" void kernel_launch(void* const* d_in, const int* in_sizes, int n_in,
                              void* d_out, int out_size) {
    const float* coords = (const float*)d_in[0];
    const int*   ri     = (const int*)d_in[1];
    const int*   rj     = (const int*)d_in[2];
    float*       out    = (float*)d_out;
    int npts = in_sizes[0] / 6;

    const size_t SMEM = (size_t)(NPV * KVAL            // psi
                                 + NPV * PV_STRIDE     // chains
                                 + 2 * NM * NM         // AB (float2)
                                 + 2 * NM)             // seed, c1
                        * sizeof(float);
    cudaFuncSetAttribute((const void*)sh_kernel,
                         cudaFuncAttributeMaxDynamicSharedMemorySize, (int)SMEM);

    init_tables_kernel<<<1, 512>>>(ri, rj);
    int grid = (npts + BPTS - 1) / BPTS;
    sh_kernel<<<grid, NTHREADS, SMEM>>>(coords, out, npts);
}